// round 15
// baseline (speedup 1.0000x reference)
#include <cuda_runtime.h>

// ScatterLoss — per-class contrastive hinge loss.
// d_in[0] = output [N, D] float32 (N=65536, D=512)
// d_in[1] = label_id [N] int32
// out     = scalar float32
//
// loss = (1/N) * sum_k cnt_k * relu(1 - || s_k/c_k - (T - s_k)/(N - c_k) + 1e-6 ||_2)^2

#define NCLS 512
#define DDIM 512
#define NF4  (DDIM / 4)   // 128 float4 columns
#define CAP  1024         // g_idx slots per class (8 segments of 128)
#define SEG  (CAP / 8)    // 128 slots per bank segment (mean ~16/bank, safe)
#define NSPL 4            // class split factor for the streaming kernel
#define PAD  32           // words per 128B line — atomic-target padding
#define CBANK 8           // counter banks per class (words 0..7 of its line)
#define DBANK 8           // d2 accumulator banks per class

// Zeroed each replay by one memset node (0 bits == 0.0f == 0).
struct ZeroBlk {
    int   cnt[NCLS * PAD];  // words 0..7 of each class line = banked counters
    float d2[NCLS * PAD];   // words 0..7 of each class line = banked d2
    unsigned int ticket;
};
static __device__ ZeroBlk g_z;

static __device__ int   g_idx[NCLS * CAP];
static __device__ float g_sumsp[NSPL][NCLS][DDIM];   // per-quarter class sums

// ---------------------------------------------------------------------------
// K1: counting-sort scatter with BANKED counters (R13's d2-bank trick applied
// to the ingest side). Bank = (i>>2)&7: each warp spreads its 32 labels over
// all 8 banks -> atomics per address drop 128 -> 16, killing the L2 atomic
// serialization floor that held this kernel at 5.5us.
// ---------------------------------------------------------------------------
__global__ void k_scatter(const int* __restrict__ lab, int N)
{
    int i = blockIdx.x * blockDim.x + threadIdx.x;
    if (i < N) {
        int k = lab[i];
        if ((unsigned)k < NCLS) {
            int b = (i >> 2) & (CBANK - 1);
            int pos = atomicAdd(&g_z.cnt[k * PAD + b], 1);
            if (pos < SEG) g_idx[k * CAP + b * SEG + pos] = i;
        }
    }
}

// ---------------------------------------------------------------------------
// K2: per-class partial sums. Four CTAs per class; CTA h walks bank segments
// {2h, 2h+1} (~32 rows total, same as the proven quarter split). Warp-uniform
// index loads (broadcast); 2KB coalesced float4 rows, __ldcs evict-first.
// Reads the full 128 MB matrix exactly once -> HBM bound (dominant kernel).
// ---------------------------------------------------------------------------
__global__ void __launch_bounds__(128) k_class_sum_q(const float* __restrict__ out)
{
    int k = blockIdx.x >> 2;
    int h = blockIdx.x & 3;
    int q = threadIdx.x;  // float4 column 0..127

    float4 acc = make_float4(0.f, 0.f, 0.f, 0.f);
    #pragma unroll
    for (int bb = 0; bb < 2; bb++) {
        int b  = h * 2 + bb;
        int nb = min(g_z.cnt[k * PAD + b], SEG);
        const int* idx = g_idx + k * CAP + b * SEG;
        #pragma unroll 16
        for (int j = 0; j < nb; j++) {
            int r = __ldg(idx + j);                   // uniform -> broadcast
            const float4* row = (const float4*)(out + (size_t)r * DDIM);
            float4 v = __ldcs(row + q);               // read-once: evict-first
            acc.x += v.x; acc.y += v.y; acc.z += v.z; acc.w += v.w;
        }
    }
    ((float4*)g_sumsp[h][k])[q] = acc;
}

// ---------------------------------------------------------------------------
// K3: grand-total + per-class d^2 partials + last-CTA finalize (R13-proven).
// 128 CTAs (one float4-column each) x 256 threads (2 classes each); banked
// d^2 deposits (16 atomics/address); last CTA folds banks + hinge + mean.
// Class count c = sum of the 8 banked counters (one L2 line).
// ---------------------------------------------------------------------------
__device__ __forceinline__ int class_count(int k)
{
    int c = 0;
    #pragma unroll
    for (int b = 0; b < CBANK; b++) c += g_z.cnt[k * PAD + b];
    return c;
}

__global__ void __launch_bounds__(256) k_colloss(float* __restrict__ outp, float fN)
{
    __shared__ float4 red[256];
    __shared__ unsigned int s_tkt;
    int cg = blockIdx.x;               // this CTA's float4 column
    int t  = threadIdx.x;
    int bank = blockIdx.x & (DBANK - 1);

    // fold the 4 quarter-sums for 2 classes
    float4 s[2];
    #pragma unroll
    for (int m = 0; m < 2; m++) {
        int k = t + m * 256;
        float4 a = make_float4(0.f, 0.f, 0.f, 0.f);
        #pragma unroll
        for (int h = 0; h < NSPL; h++) {
            float4 v = ((const float4*)g_sumsp[h][k])[cg];
            a.x += v.x; a.y += v.y; a.z += v.z; a.w += v.w;
        }
        s[m] = a;
    }

    // grand total T for this column (one 8-level tree)
    float4 x;
    x.x = s[0].x + s[1].x; x.y = s[0].y + s[1].y;
    x.z = s[0].z + s[1].z; x.w = s[0].w + s[1].w;
    red[t] = x;
    __syncthreads();
    #pragma unroll
    for (int sh = 128; sh > 0; sh >>= 1) {
        if (t < sh) {
            float4 b = red[t + sh];
            red[t].x += b.x; red[t].y += b.y; red[t].z += b.z; red[t].w += b.w;
        }
        __syncthreads();
    }
    float4 T = red[0];

    // per-class d^2 over this column's 4 dims -> banked atomic deposit
    #pragma unroll
    for (int m = 0; m < 2; m++) {
        int k = t + m * 256;
        int c = class_count(k);
        if (c > 0) {
            float fc  = (float)c;
            float ip  = 1.f / fc;
            float in_ = 1.f / (fN - fc);
            float dx = s[m].x * ip - (T.x - s[m].x) * in_ + 1e-6f;
            float dy = s[m].y * ip - (T.y - s[m].y) * in_ + 1e-6f;
            float dz = s[m].z * ip - (T.z - s[m].z) * in_ + 1e-6f;
            float dw = s[m].w * ip - (T.w - s[m].w) * in_ + 1e-6f;
            float p  = dx * dx + dy * dy + dz * dz + dw * dw;
            atomicAdd(&g_z.d2[k * PAD + bank], p);
        }
    }

    // last-CTA finalize
    __threadfence();
    __syncthreads();
    if (t == 0) s_tkt = atomicAdd(&g_z.ticket, 1u);
    __syncthreads();
    if (s_tkt == (unsigned)(gridDim.x - 1)) {
        __threadfence();
        float w = 0.f;
        #pragma unroll
        for (int m = 0; m < 2; m++) {
            int k = t + m * 256;
            int c = class_count(k);
            if (c > 0) {
                float d2 = 0.f;
                #pragma unroll
                for (int b = 0; b < DBANK; b++)
                    d2 += g_z.d2[k * PAD + b];
                float dist = sqrtf(d2);
                float mg = fmaxf(1.0f - dist, 0.f);   // MARGIN = 1.0
                w += (float)c * mg * mg;
            }
        }
        float* fr = (float*)red;
        fr[t] = w;
        __syncthreads();
        #pragma unroll
        for (int sh = 128; sh > 0; sh >>= 1) {
            if (t < sh) fr[t] += fr[t + sh];
            __syncthreads();
        }
        if (t == 0) outp[0] = fr[0] / fN;
    }
}

// ---------------------------------------------------------------------------
extern "C" void kernel_launch(void* const* d_in, const int* in_sizes, int n_in,
                              void* d_out, int out_size)
{
    const float* output = (const float*)d_in[0];
    const int*   label  = (const int*)d_in[1];
    int N = in_sizes[1];

    void* zptr = nullptr;
    cudaGetSymbolAddress(&zptr, g_z);            // host-side query; capture-safe
    cudaMemsetAsync(zptr, 0, sizeof(ZeroBlk));   // banked counters + d2 + ticket

    k_scatter<<<(N + 255) / 256, 256>>>(label, N);
    k_class_sum_q<<<NCLS * NSPL, 128>>>(output);
    k_colloss<<<NF4, 256>>>((float*)d_out, (float)N);
}

// round 16
// speedup vs baseline: 1.2626x; 1.2626x over previous
#include <cuda_runtime.h>

// ScatterLoss — per-class contrastive hinge loss.
// d_in[0] = output [N, D] float32 (N=65536, D=512)
// d_in[1] = label_id [N] int32
// out     = scalar float32
//
// loss = (1/N) * sum_k cnt_k * relu(1 - || s_k/c_k - (T - s_k)/(N - c_k) + 1e-6 ||_2)^2

#define NCLS 512
#define DDIM 512
#define NF4  (DDIM / 4)   // 128 float4 columns
#define CAP  1024         // max rows per class (counts ~128±11)
#define NSPL 4            // class split factor for the streaming kernel
#define PAD  32           // words per 128B line — atomic-target padding
#define DOFF 8            // d2 banks live at words 8..15 of the class line
#define DBANK 8           // d2 accumulator banks per class

// One 128B line per class: word 0 = counter (same address as the proven R13
// layout), words 8..15 = banked d2 partials. Zeroed each replay by ONE 64KB
// memset node (half the zero-traffic of the split layout).
struct ZeroBlk {
    unsigned int line[NCLS * PAD];  // int/float punned via atomics
    unsigned int ticket;
};
static __device__ ZeroBlk g_z;

static __device__ int   g_idx[NCLS * CAP];
static __device__ float g_sumsp[NSPL][NCLS][DDIM];   // per-quarter class sums

__device__ __forceinline__ int*   cnt_addr(int k) { return (int*)&g_z.line[k * PAD]; }
__device__ __forceinline__ float* d2_addr(int k, int b) { return (float*)&g_z.line[k * PAD + DOFF + b]; }

// ---------------------------------------------------------------------------
// K1: counting-sort scatter (proven floor: one thread per label, ~5.5us —
// bound by the load->atomic->store chain, not atomic throughput).
// Padded counters: 65K atomics over 512 distinct 128B lines.
// ---------------------------------------------------------------------------
__global__ void k_scatter(const int* __restrict__ lab, int N)
{
    int i = blockIdx.x * blockDim.x + threadIdx.x;
    if (i < N) {
        int k = lab[i];
        if ((unsigned)k < NCLS) {
            int pos = atomicAdd(cnt_addr(k), 1);
            if (pos < CAP) g_idx[k * CAP + pos] = i;
        }
    }
}

// ---------------------------------------------------------------------------
// K2: per-class partial sums — byte-identical hot loop to the 36.96us best.
// Four CTAs per class, contiguous quarters of the (near-sorted) row list:
// single ~32-trip loop (front-batched loads, good per-CTA row locality).
// Warp-uniform index loads (broadcast); 2KB coalesced float4 rows, __ldcs.
// Reads the full 128 MB matrix exactly once -> HBM bound (dominant kernel).
// ---------------------------------------------------------------------------
__global__ void __launch_bounds__(128) k_class_sum_q(const float* __restrict__ out)
{
    int k  = blockIdx.x >> 2;
    int h  = blockIdx.x & 3;
    int nk = min(*cnt_addr(k), CAP);
    int j0 = (h * nk) >> 2;
    int j1 = ((h + 1) * nk) >> 2;
    int nj = j1 - j0;

    const int* idx = g_idx + k * CAP + j0;
    int q = threadIdx.x;  // float4 column 0..127

    float4 acc = make_float4(0.f, 0.f, 0.f, 0.f);
    #pragma unroll 16
    for (int j = 0; j < nj; j++) {
        int r = __ldg(idx + j);                       // uniform -> broadcast
        const float4* row = (const float4*)(out + (size_t)r * DDIM);
        float4 v = __ldcs(row + q);                   // read-once: evict-first
        acc.x += v.x; acc.y += v.y; acc.z += v.z; acc.w += v.w;
    }
    ((float4*)g_sumsp[h][k])[q] = acc;
}

// ---------------------------------------------------------------------------
// K3: grand-total + per-class d^2 partials + last-CTA finalize (R13-proven).
// 128 CTAs (one float4-column each, near-full chip) x 256 threads (2 classes
// each). Banked d^2 deposits: bank = blockIdx&7 -> 16 atomics/address.
// Last CTA folds the 8 banks per class, applies the hinge, writes the mean.
// ---------------------------------------------------------------------------
__global__ void __launch_bounds__(256) k_colloss(float* __restrict__ outp, float fN)
{
    __shared__ float4 red[256];
    __shared__ unsigned int s_tkt;
    int cg = blockIdx.x;               // this CTA's float4 column
    int t  = threadIdx.x;
    int bank = blockIdx.x & (DBANK - 1);

    // fold the 4 quarter-sums for 2 classes
    float4 s[2];
    #pragma unroll
    for (int m = 0; m < 2; m++) {
        int k = t + m * 256;
        float4 a = make_float4(0.f, 0.f, 0.f, 0.f);
        #pragma unroll
        for (int h = 0; h < NSPL; h++) {
            float4 v = ((const float4*)g_sumsp[h][k])[cg];
            a.x += v.x; a.y += v.y; a.z += v.z; a.w += v.w;
        }
        s[m] = a;
    }

    // grand total T for this column (one 8-level tree)
    float4 x;
    x.x = s[0].x + s[1].x; x.y = s[0].y + s[1].y;
    x.z = s[0].z + s[1].z; x.w = s[0].w + s[1].w;
    red[t] = x;
    __syncthreads();
    #pragma unroll
    for (int sh = 128; sh > 0; sh >>= 1) {
        if (t < sh) {
            float4 b = red[t + sh];
            red[t].x += b.x; red[t].y += b.y; red[t].z += b.z; red[t].w += b.w;
        }
        __syncthreads();
    }
    float4 T = red[0];

    // per-class d^2 over this column's 4 dims -> banked atomic deposit
    #pragma unroll
    for (int m = 0; m < 2; m++) {
        int k = t + m * 256;
        int c = *cnt_addr(k);
        if (c > 0) {
            float fc  = (float)c;
            float ip  = 1.f / fc;
            float in_ = 1.f / (fN - fc);
            float dx = s[m].x * ip - (T.x - s[m].x) * in_ + 1e-6f;
            float dy = s[m].y * ip - (T.y - s[m].y) * in_ + 1e-6f;
            float dz = s[m].z * ip - (T.z - s[m].z) * in_ + 1e-6f;
            float dw = s[m].w * ip - (T.w - s[m].w) * in_ + 1e-6f;
            float p  = dx * dx + dy * dy + dz * dz + dw * dw;
            atomicAdd(d2_addr(k, bank), p);
        }
    }

    // last-CTA finalize
    __threadfence();
    __syncthreads();
    if (t == 0) s_tkt = atomicAdd(&g_z.ticket, 1u);
    __syncthreads();
    if (s_tkt == (unsigned)(gridDim.x - 1)) {
        __threadfence();
        float w = 0.f;
        #pragma unroll
        for (int m = 0; m < 2; m++) {
            int k = t + m * 256;
            int c = *cnt_addr(k);
            if (c > 0) {
                float d2 = 0.f;
                #pragma unroll
                for (int b = 0; b < DBANK; b++)
                    d2 += *d2_addr(k, b);
                float dist = sqrtf(d2);
                float mg = fmaxf(1.0f - dist, 0.f);   // MARGIN = 1.0
                w += (float)c * mg * mg;
            }
        }
        float* fr = (float*)red;
        fr[t] = w;
        __syncthreads();
        #pragma unroll
        for (int sh = 128; sh > 0; sh >>= 1) {
            if (t < sh) fr[t] += fr[t + sh];
            __syncthreads();
        }
        if (t == 0) outp[0] = fr[0] / fN;
    }
}

// ---------------------------------------------------------------------------
extern "C" void kernel_launch(void* const* d_in, const int* in_sizes, int n_in,
                              void* d_out, int out_size)
{
    const float* output = (const float*)d_in[0];
    const int*   label  = (const int*)d_in[1];
    int N = in_sizes[1];

    void* zptr = nullptr;
    cudaGetSymbolAddress(&zptr, g_z);            // host-side query; capture-safe
    cudaMemsetAsync(zptr, 0, sizeof(ZeroBlk));   // one 64KB line region + ticket

    k_scatter<<<(N + 255) / 256, 256>>>(label, N);
    k_class_sum_q<<<NCLS * NSPL, 128>>>(output);
    k_colloss<<<NF4, 256>>>((float*)d_out, (float)N);
}

// round 17
// speedup vs baseline: 1.2790x; 1.0130x over previous
#include <cuda_runtime.h>

// ScatterLoss — per-class contrastive hinge loss.
// d_in[0] = output [N, D] float32 (N=65536, D=512)
// d_in[1] = label_id [N] int32
// out     = scalar float32
//
// loss = (1/N) * sum_k cnt_k * relu(1 - || s_k/c_k - (T - s_k)/(N - c_k) + 1e-6 ||_2)^2

#define NCLS 512
#define DDIM 512
#define NF4  (DDIM / 4)   // 128 float4 columns
#define CAP  1024         // max rows per class (counts ~128±11)
#define NSPL 4            // class split factor for the streaming kernel
#define PAD  32           // words per 128B line — atomic-target padding
#define DOFF 8            // d2 banks live at words 8..15 of the class line
#define DBANK 8           // d2 accumulator banks per class

// One 128B line per class: word 0 = counter, words 8..15 = banked d2.
// SELF-CLEANING: statically zero-initialized for the first run; thereafter
// the finalize CTA of k_colloss re-zeroes the whole region at its tail, so
// NO memset node is needed in the graph (4 nodes -> 3).
struct ZeroBlk {
    unsigned int line[NCLS * PAD];  // 64KB
    unsigned int ticket;
};
static __device__ ZeroBlk g_z;      // zero-initialized at module load

static __device__ int   g_idx[NCLS * CAP];
static __device__ float g_sumsp[NSPL][NCLS][DDIM];   // per-quarter class sums

__device__ __forceinline__ int*   cnt_addr(int k) { return (int*)&g_z.line[k * PAD]; }
__device__ __forceinline__ float* d2_addr(int k, int b) { return (float*)&g_z.line[k * PAD + DOFF + b]; }

// ---------------------------------------------------------------------------
// K1: counting-sort scatter (proven floor ~5.5us: load->atomic->store chain).
// 128 CTAs x 512 threads: same 65K threads, half the CTA ramp.
// Padded counters: 65K atomics over 512 distinct 128B lines.
// ---------------------------------------------------------------------------
__global__ void __launch_bounds__(512) k_scatter(const int* __restrict__ lab, int N)
{
    int i = blockIdx.x * blockDim.x + threadIdx.x;
    if (i < N) {
        int k = lab[i];
        if ((unsigned)k < NCLS) {
            int pos = atomicAdd(cnt_addr(k), 1);
            if (pos < CAP) g_idx[k * CAP + pos] = i;
        }
    }
}

// ---------------------------------------------------------------------------
// K2: per-class partial sums — byte-identical hot loop to the 36.96us best.
// Four CTAs per class, contiguous quarters of the (near-sorted) row list;
// warp-uniform index loads (broadcast); 2KB coalesced float4 rows, __ldcs.
// Reads the full 128 MB matrix exactly once -> HBM bound (dominant kernel).
// ---------------------------------------------------------------------------
__global__ void __launch_bounds__(128) k_class_sum_q(const float* __restrict__ out)
{
    int k  = blockIdx.x >> 2;
    int h  = blockIdx.x & 3;
    int nk = min(*cnt_addr(k), CAP);
    int j0 = (h * nk) >> 2;
    int j1 = ((h + 1) * nk) >> 2;
    int nj = j1 - j0;

    const int* idx = g_idx + k * CAP + j0;
    int q = threadIdx.x;  // float4 column 0..127

    float4 acc = make_float4(0.f, 0.f, 0.f, 0.f);
    #pragma unroll 16
    for (int j = 0; j < nj; j++) {
        int r = __ldg(idx + j);                       // uniform -> broadcast
        const float4* row = (const float4*)(out + (size_t)r * DDIM);
        float4 v = __ldcs(row + q);                   // read-once: evict-first
        acc.x += v.x; acc.y += v.y; acc.z += v.z; acc.w += v.w;
    }
    ((float4*)g_sumsp[h][k])[q] = acc;
}

// ---------------------------------------------------------------------------
// K3: grand-total + per-class d^2 partials + last-CTA finalize + SELF-CLEAN.
// 128 CTAs (one float4-column each) x 256 threads (2 classes each); banked
// d^2 deposits (16 atomics/address). The finalize CTA — after its reads —
// zeroes the whole ZeroBlk for the next graph replay.
// ---------------------------------------------------------------------------
__global__ void __launch_bounds__(256) k_colloss(float* __restrict__ outp, float fN)
{
    __shared__ float4 red[256];
    __shared__ unsigned int s_tkt;
    int cg = blockIdx.x;               // this CTA's float4 column
    int t  = threadIdx.x;
    int bank = blockIdx.x & (DBANK - 1);

    // fold the 4 quarter-sums for 2 classes
    float4 s[2];
    #pragma unroll
    for (int m = 0; m < 2; m++) {
        int k = t + m * 256;
        float4 a = make_float4(0.f, 0.f, 0.f, 0.f);
        #pragma unroll
        for (int h = 0; h < NSPL; h++) {
            float4 v = ((const float4*)g_sumsp[h][k])[cg];
            a.x += v.x; a.y += v.y; a.z += v.z; a.w += v.w;
        }
        s[m] = a;
    }

    // grand total T for this column (one 8-level tree)
    float4 x;
    x.x = s[0].x + s[1].x; x.y = s[0].y + s[1].y;
    x.z = s[0].z + s[1].z; x.w = s[0].w + s[1].w;
    red[t] = x;
    __syncthreads();
    #pragma unroll
    for (int sh = 128; sh > 0; sh >>= 1) {
        if (t < sh) {
            float4 b = red[t + sh];
            red[t].x += b.x; red[t].y += b.y; red[t].z += b.z; red[t].w += b.w;
        }
        __syncthreads();
    }
    float4 T = red[0];

    // per-class d^2 over this column's 4 dims -> banked atomic deposit
    #pragma unroll
    for (int m = 0; m < 2; m++) {
        int k = t + m * 256;
        int c = *cnt_addr(k);
        if (c > 0) {
            float fc  = (float)c;
            float ip  = 1.f / fc;
            float in_ = 1.f / (fN - fc);
            float dx = s[m].x * ip - (T.x - s[m].x) * in_ + 1e-6f;
            float dy = s[m].y * ip - (T.y - s[m].y) * in_ + 1e-6f;
            float dz = s[m].z * ip - (T.z - s[m].z) * in_ + 1e-6f;
            float dw = s[m].w * ip - (T.w - s[m].w) * in_ + 1e-6f;
            float p  = dx * dx + dy * dy + dz * dz + dw * dw;
            atomicAdd(d2_addr(k, bank), p);
        }
    }

    // last-CTA finalize
    __threadfence();
    __syncthreads();
    if (t == 0) s_tkt = atomicAdd(&g_z.ticket, 1u);
    __syncthreads();
    if (s_tkt == (unsigned)(gridDim.x - 1)) {
        __threadfence();
        float w = 0.f;
        #pragma unroll
        for (int m = 0; m < 2; m++) {
            int k = t + m * 256;
            int c = *cnt_addr(k);
            if (c > 0) {
                float d2 = 0.f;
                #pragma unroll
                for (int b = 0; b < DBANK; b++)
                    d2 += *d2_addr(k, b);
                float dist = sqrtf(d2);
                float mg = fmaxf(1.0f - dist, 0.f);   // MARGIN = 1.0
                w += (float)c * mg * mg;
            }
        }
        float* fr = (float*)red;
        fr[t] = w;
        __syncthreads();
        #pragma unroll
        for (int sh = 128; sh > 0; sh >>= 1) {
            if (t < sh) fr[t] += fr[t + sh];
            __syncthreads();
        }
        if (t == 0) outp[0] = fr[0] / fN;
        __syncthreads();

        // ---- self-clean for the next replay (all reads above are done) ----
        uint4 z4 = make_uint4(0u, 0u, 0u, 0u);
        uint4* base = (uint4*)g_z.line;              // 64KB = 4096 uint4
        #pragma unroll
        for (int j = 0; j < (NCLS * PAD / 4) / 256; j++)
            base[t + j * 256] = z4;
        if (t == 0) g_z.ticket = 0u;
    }
}

// ---------------------------------------------------------------------------
extern "C" void kernel_launch(void* const* d_in, const int* in_sizes, int n_in,
                              void* d_out, int out_size)
{
    const float* output = (const float*)d_in[0];
    const int*   label  = (const int*)d_in[1];
    int N = in_sizes[1];

    // No memset node: g_z starts zeroed (static init) and k_colloss's
    // finalize CTA re-zeroes it at the end of every execution.
    k_scatter<<<(N + 511) / 512, 512>>>(label, N);
    k_class_sum_q<<<NCLS * NSPL, 128>>>(output);
    k_colloss<<<NF4, 256>>>((float*)d_out, (float)N);
}